// round 2
// baseline (speedup 1.0000x reference)
#include <cuda_runtime.h>

// Problem constants
#define BATCH 2
#define SEQ   4096
#define DMODEL 512
#define NHEAD 8
#define HEADD 64
#define MTOT  (BATCH * SEQ)          // 8192 rows for projections
#define PS_STRIDE 65                 // padded stride for the P tile (bank-conflict-free row scans)

// Scratch (device globals: allocation-free per harness rules). 4 x 16 MB.
__device__ float g_q[BATCH * SEQ * DMODEL];
__device__ float g_k[BATCH * SEQ * DMODEL];
__device__ float g_v[BATCH * SEQ * DMODEL];
__device__ float g_attn[BATCH * SEQ * DMODEL];

// ---------------------------------------------------------------------------
// GEMM: C[M,N] = A[M,K] @ W[K,N] + bias[N]
// 64x64 block tile, 16-deep K slices, 256 threads, 4x4 register micro-tile.
// ---------------------------------------------------------------------------
__global__ __launch_bounds__(256) void gemm_bias_kernel(
    const float* __restrict__ A, const float* __restrict__ W,
    const float* __restrict__ bias, float* __restrict__ C,
    int M, int N, int K)
{
    __shared__ __align__(16) float As[16][64];  // [k][m] (transposed on load)
    __shared__ __align__(16) float Bs[16][64];  // [k][n]

    const int tid = threadIdx.x;
    const int tx = tid & 15;        // 0..15 -> N micro
    const int ty = tid >> 4;        // 0..15 -> M micro
    const int row0 = blockIdx.y * 64;
    const int col0 = blockIdx.x * 64;

    float acc[4][4] = {};

    for (int k0 = 0; k0 < K; k0 += 16) {
        // Load A tile (64 rows x 16 k), store transposed into As[k][m]
        {
            int r  = tid >> 2;          // 0..63
            int kv = (tid & 3) * 4;     // 0,4,8,12
            float4 a4 = *(const float4*)&A[(size_t)(row0 + r) * K + k0 + kv];
            As[kv + 0][r] = a4.x;
            As[kv + 1][r] = a4.y;
            As[kv + 2][r] = a4.z;
            As[kv + 3][r] = a4.w;
        }
        // Load W tile (16 k x 64 n) directly
        {
            int r  = tid >> 4;          // 0..15
            int cv = (tid & 15) * 4;    // 0..60
            *(float4*)&Bs[r][cv] = *(const float4*)&W[(size_t)(k0 + r) * N + col0 + cv];
        }
        __syncthreads();

        #pragma unroll
        for (int kk = 0; kk < 16; kk++) {
            float4 a4 = *(const float4*)&As[kk][ty * 4];
            float4 b4 = *(const float4*)&Bs[kk][tx * 4];
            float a[4] = {a4.x, a4.y, a4.z, a4.w};
            float b[4] = {b4.x, b4.y, b4.z, b4.w};
            #pragma unroll
            for (int i = 0; i < 4; i++)
                #pragma unroll
                for (int j = 0; j < 4; j++)
                    acc[i][j] += a[i] * b[j];
        }
        __syncthreads();
    }

    #pragma unroll
    for (int i = 0; i < 4; i++) {
        int r = row0 + ty * 4 + i;
        #pragma unroll
        for (int j = 0; j < 4; j++) {
            int c = col0 + tx * 4 + j;
            C[(size_t)r * N + c] = acc[i][j] + bias[c];
        }
    }
}

// ---------------------------------------------------------------------------
// Flash attention (fp32, causal, online softmax).
// Grid: (SEQ/64, NHEAD, BATCH). Block: 256 threads.
// Each block: 64 queries x full head. Key tiles of 64.
// Dynamic smem layout (floats):
//   Qs [64k][64r]  @ 0
//   Ks [64k][64c]  @ 4096
//   Vs [64k][64c]  @ 8192
//   Ps [64r][65]   @ 12288  (padded stride)
//   mrow[64] lrow[64] arow[64] after Ps
// ---------------------------------------------------------------------------
#define ATTN_SMEM_FLOATS (12288 + 64 * PS_STRIDE + 3 * 64)
#define ATTN_SMEM_BYTES  (ATTN_SMEM_FLOATS * 4)

__global__ __launch_bounds__(256) void attn_kernel(
    const float* __restrict__ Q, const float* __restrict__ K,
    const float* __restrict__ V, float* __restrict__ O)
{
    extern __shared__ __align__(16) float sm[];
    float* Qs   = sm;                       // [k][r]
    float* Ks   = sm + 4096;                // [k][c]
    float* Vs   = sm + 8192;                // [kk][c]
    float* Ps   = sm + 12288;               // [r][PS_STRIDE]
    float* mrow = Ps + 64 * PS_STRIDE;
    float* lrow = mrow + 64;
    float* arow = lrow + 64;

    const int qt = blockIdx.x;
    const int h  = blockIdx.y;
    const int b  = blockIdx.z;
    const int q0 = qt * 64;
    const int tid = threadIdx.x;
    const int tx = tid & 15;
    const int ty = tid >> 4;
    const size_t base = (size_t)b * SEQ * DMODEL + (size_t)h * HEADD;

    // Load Q tile transposed: Qs[k][r]
    #pragma unroll
    for (int i = 0; i < 4; i++) {
        int p  = tid + i * 256;       // 0..1023
        int r  = p >> 4;              // 0..63
        int kv = (p & 15) * 4;        // 0..60
        float4 q4 = *(const float4*)&Q[base + (size_t)(q0 + r) * DMODEL + kv];
        Qs[(kv + 0) * 64 + r] = q4.x;
        Qs[(kv + 1) * 64 + r] = q4.y;
        Qs[(kv + 2) * 64 + r] = q4.z;
        Qs[(kv + 3) * 64 + r] = q4.w;
    }
    if (tid < 64) { mrow[tid] = -1e30f; lrow[tid] = 0.0f; }

    float o[4][4] = {};
    __syncthreads();

    for (int kt = 0; kt <= qt; kt++) {
        const int k0 = kt * 64;
        // Load K (transposed) and V (direct) tiles
        #pragma unroll
        for (int i = 0; i < 4; i++) {
            int p  = tid + i * 256;
            int r  = p >> 4;
            int kv = (p & 15) * 4;
            float4 k4 = *(const float4*)&K[base + (size_t)(k0 + r) * DMODEL + kv];
            Ks[(kv + 0) * 64 + r] = k4.x;
            Ks[(kv + 1) * 64 + r] = k4.y;
            Ks[(kv + 2) * 64 + r] = k4.z;
            Ks[(kv + 3) * 64 + r] = k4.w;
            float4 v4 = *(const float4*)&V[base + (size_t)(k0 + r) * DMODEL + kv];
            *(float4*)&Vs[r * 64 + kv] = v4;
        }
        __syncthreads();

        // GEMM1: S = Q K^T (64x64x64)
        float s[4][4] = {};
        #pragma unroll 16
        for (int kk = 0; kk < 64; kk++) {
            float4 a4 = *(const float4*)&Qs[kk * 64 + ty * 4];
            float4 b4 = *(const float4*)&Ks[kk * 64 + tx * 4];
            float a[4] = {a4.x, a4.y, a4.z, a4.w};
            float c[4] = {b4.x, b4.y, b4.z, b4.w};
            #pragma unroll
            for (int i = 0; i < 4; i++)
                #pragma unroll
                for (int j = 0; j < 4; j++)
                    s[i][j] += a[i] * c[j];
        }
        const bool diag = (kt == qt);
        #pragma unroll
        for (int i = 0; i < 4; i++) {
            int r = ty * 4 + i;
            #pragma unroll
            for (int j = 0; j < 4; j++) {
                int c = tx * 4 + j;
                float val = s[i][j] * 0.125f;   // 1/sqrt(64)
                if (diag && (k0 + c > q0 + r)) val = -1e30f;
                Ps[r * PS_STRIDE + c] = val;
            }
        }
        __syncthreads();

        // Online softmax per row (threads 0..63 own one row each)
        if (tid < 64) {
            const int r = tid;
            float m0 = mrow[r];
            float mn = m0;
            #pragma unroll 8
            for (int c = 0; c < 64; c++)
                mn = fmaxf(mn, Ps[r * PS_STRIDE + c]);
            float al = __expf(m0 - mn);
            float ln = lrow[r] * al;
            #pragma unroll 8
            for (int c = 0; c < 64; c++) {
                float p = __expf(Ps[r * PS_STRIDE + c] - mn);
                Ps[r * PS_STRIDE + c] = p;
                ln += p;
            }
            mrow[r] = mn;
            lrow[r] = ln;
            arow[r] = al;
        }
        __syncthreads();

        // Rescale accumulators, then GEMM2: O += P V (64x64x64)
        float al[4];
        #pragma unroll
        for (int i = 0; i < 4; i++) al[i] = arow[ty * 4 + i];
        #pragma unroll
        for (int i = 0; i < 4; i++)
            #pragma unroll
            for (int j = 0; j < 4; j++)
                o[i][j] *= al[i];

        #pragma unroll 16
        for (int kk = 0; kk < 64; kk++) {
            float4 v4 = *(const float4*)&Vs[kk * 64 + tx * 4];
            float vv[4] = {v4.x, v4.y, v4.z, v4.w};
            float p[4];
            #pragma unroll
            for (int i = 0; i < 4; i++) p[i] = Ps[(ty * 4 + i) * PS_STRIDE + kk];
            #pragma unroll
            for (int i = 0; i < 4; i++)
                #pragma unroll
                for (int j = 0; j < 4; j++)
                    o[i][j] += p[i] * vv[j];
        }
        __syncthreads();
    }

    // Normalize and write attention output in [b, s, h*HD + hd] layout
    #pragma unroll
    for (int i = 0; i < 4; i++) {
        int r = ty * 4 + i;
        float inv = 1.0f / lrow[r];
        #pragma unroll
        for (int j = 0; j < 4; j++) {
            int c = tx * 4 + j;
            O[base + (size_t)(q0 + r) * DMODEL + c] = o[i][j] * inv;
        }
    }
}

// ---------------------------------------------------------------------------
// Launch
// ---------------------------------------------------------------------------
extern "C" void kernel_launch(void* const* d_in, const int* in_sizes, int n_in,
                              void* d_out, int out_size)
{
    const float* x  = (const float*)d_in[0];
    const float* Wq = (const float*)d_in[1];
    const float* bq = (const float*)d_in[2];
    const float* Wk = (const float*)d_in[3];
    const float* bk = (const float*)d_in[4];
    const float* Wv = (const float*)d_in[5];
    const float* bv = (const float*)d_in[6];
    const float* Wo = (const float*)d_in[7];
    const float* bo = (const float*)d_in[8];
    float* out = (float*)d_out;

    float *q, *k, *v, *attn;
    cudaGetSymbolAddress((void**)&q,    g_q);
    cudaGetSymbolAddress((void**)&k,    g_k);
    cudaGetSymbolAddress((void**)&v,    g_v);
    cudaGetSymbolAddress((void**)&attn, g_attn);

    cudaFuncSetAttribute(attn_kernel,
                         cudaFuncAttributeMaxDynamicSharedMemorySize,
                         ATTN_SMEM_BYTES);

    dim3 ggrid(DMODEL / 64, MTOT / 64);   // (8, 128)
    gemm_bias_kernel<<<ggrid, 256>>>(x, Wq, bq, q, MTOT, DMODEL, DMODEL);
    gemm_bias_kernel<<<ggrid, 256>>>(x, Wk, bk, k, MTOT, DMODEL, DMODEL);
    gemm_bias_kernel<<<ggrid, 256>>>(x, Wv, bv, v, MTOT, DMODEL, DMODEL);

    dim3 agrid(SEQ / 64, NHEAD, BATCH);   // (64, 8, 2)
    attn_kernel<<<agrid, 256, ATTN_SMEM_BYTES>>>(q, k, v, attn);

    gemm_bias_kernel<<<ggrid, 256>>>(attn, Wo, bo, out, MTOT, DMODEL, DMODEL);
}

// round 4
// speedup vs baseline: 3.0268x; 3.0268x over previous
#include <cuda_runtime.h>
#include <cuda_bf16.h>
#include <cstdint>

// ===========================================================================
// Problem: B=2, S=4096, D=512, H=8, HD=64
// ===========================================================================
#define BATCH 2
#define SEQ   4096
#define DMODEL 512
#define NHEAD 8
#define HEADD 64
#define MTOT  (BATCH * SEQ)   // 8192

// ===========================================================================
// Helpers
// ===========================================================================
__device__ __forceinline__ uint32_t smem_u32(const void* p) {
    uint32_t a;
    asm("{ .reg .u64 t; cvta.to.shared.u64 t, %1; cvt.u32.u64 %0, t; }"
        : "=r"(a) : "l"(p));
    return a;
}

__device__ __forceinline__ void ldmx4(uint32_t r[4], uint32_t a) {
    asm volatile("ldmatrix.sync.aligned.m8n8.x4.shared.b16 {%0,%1,%2,%3}, [%4];"
                 : "=r"(r[0]), "=r"(r[1]), "=r"(r[2]), "=r"(r[3]) : "r"(a));
}
__device__ __forceinline__ void ldmx2(uint32_t r[2], uint32_t a) {
    asm volatile("ldmatrix.sync.aligned.m8n8.x2.shared.b16 {%0,%1}, [%2];"
                 : "=r"(r[0]), "=r"(r[1]) : "r"(a));
}
// D += A * B  (m16n8k16, bf16 in, f32 accum)
__device__ __forceinline__ void mma16816(float (&c)[4], const uint32_t (&a)[4],
                                         const uint32_t (&b)[2]) {
    asm volatile(
        "mma.sync.aligned.m16n8k16.row.col.f32.bf16.bf16.f32 "
        "{%0,%1,%2,%3}, {%4,%5,%6,%7}, {%8,%9}, {%0,%1,%2,%3};"
        : "+f"(c[0]), "+f"(c[1]), "+f"(c[2]), "+f"(c[3])
        : "r"(a[0]), "r"(a[1]), "r"(a[2]), "r"(a[3]), "r"(b[0]), "r"(b[1]));
}

__device__ __forceinline__ void bsplit(float v, __nv_bfloat16& h, __nv_bfloat16& l) {
    h = __float2bfloat16(v);
    l = __float2bfloat16(v - __bfloat162float(h));
}
__device__ __forceinline__ uint32_t bpack(__nv_bfloat16 a, __nv_bfloat16 b) {
    return (uint32_t)__bfloat16_as_ushort(a) |
           ((uint32_t)__bfloat16_as_ushort(b) << 16);
}

// ===========================================================================
// Scratch (device globals — allocation-free)
// ===========================================================================
__device__ __nv_bfloat16 g_xh[MTOT * DMODEL], g_xl[MTOT * DMODEL];
__device__ __nv_bfloat16 g_wth[4 * DMODEL * DMODEL], g_wtl[4 * DMODEL * DMODEL];
__device__ __nv_bfloat16 g_qh[MTOT * DMODEL], g_ql[MTOT * DMODEL];
__device__ __nv_bfloat16 g_kh[MTOT * DMODEL], g_kl[MTOT * DMODEL];
__device__ __nv_bfloat16 g_vth[MTOT * DMODEL], g_vtl[MTOT * DMODEL]; // [(b*8+h)*64+d][4096]
__device__ __nv_bfloat16 g_ah[MTOT * DMODEL], g_al[MTOT * DMODEL];

// ===========================================================================
// fp32 -> bf16 hi/lo split kernels
// ===========================================================================
__global__ void split_kernel(const float* __restrict__ x,
                             __nv_bfloat16* __restrict__ h,
                             __nv_bfloat16* __restrict__ l, int n) {
    for (int i = blockIdx.x * blockDim.x + threadIdx.x; i < n;
         i += gridDim.x * blockDim.x) {
        __nv_bfloat16 a, b;
        bsplit(x[i], a, b);
        h[i] = a; l[i] = b;
    }
}

__global__ void wsplit_kernel(const float* __restrict__ W,
                              __nv_bfloat16* __restrict__ th,
                              __nv_bfloat16* __restrict__ tl) {
    __shared__ float t[32][33];
    int bx = blockIdx.x * 32, by = blockIdx.y * 32;
    int tx = threadIdx.x, ty = threadIdx.y;
    #pragma unroll
    for (int i = 0; i < 4; i++)
        t[ty + i * 8][tx] = W[(size_t)(by + ty + i * 8) * DMODEL + bx + tx];
    __syncthreads();
    #pragma unroll
    for (int i = 0; i < 4; i++) {
        float v = t[tx][ty + i * 8];
        __nv_bfloat16 h, l;
        bsplit(v, h, l);
        size_t idx = (size_t)(bx + ty + i * 8) * DMODEL + by + tx;
        th[idx] = h; tl[idx] = l;
    }
}

// ===========================================================================
// Projection GEMM via mma.sync: C[8192,512] = A[8192,512] @ W + bias
// A bf16 hi/lo row-major; B = Wt[n][k] hi/lo (k-contig rows).
// Block 256 thr, tile 128(M)x64(N), warps 4x2, warp tile 32x32.
// mode 0: bf16 hi/lo row-major; mode 1: V transposed hi/lo; mode 2: fp32.
// ===========================================================================
#define PR_AH 0
#define PR_AL 18432
#define PR_BH 36864
#define PR_BL 46080
#define PR_SMEM 55296

__global__ __launch_bounds__(256) void gemm_mma_kernel(
    const __nv_bfloat16* __restrict__ Ah, const __nv_bfloat16* __restrict__ Al,
    const __nv_bfloat16* __restrict__ Bh, const __nv_bfloat16* __restrict__ Bl,
    const float* __restrict__ bias, int mode,
    __nv_bfloat16* __restrict__ Oh, __nv_bfloat16* __restrict__ Ol,
    float* __restrict__ Of)
{
    extern __shared__ __align__(16) char sm[];
    const uint32_t sb = smem_u32(sm);
    const int tid = threadIdx.x;
    const int lane = tid & 31, wid = tid >> 5;
    const int wm = (wid & 3) * 32, wn = (wid >> 2) * 32;
    const int col0 = blockIdx.x * 64;
    const int row0 = blockIdx.y * 128;
    const int l16 = lane & 15;

    float acc[2][4][4] = {};

    for (int chunk = 0; chunk < 8; chunk++) {
        const int kc0 = chunk * 64;
        // Load A tile 128x64 (hi/lo)
        #pragma unroll
        for (int i = 0; i < 4; i++) {
            int u = tid + i * 256;
            int row = u >> 3, c8 = u & 7;
            uint32_t so = (uint32_t)(row * 72 + c8 * 8) * 2;
            size_t g = (size_t)(row0 + row) * DMODEL + kc0 + c8 * 8;
            *(uint4*)(sm + PR_AH + so) = *(const uint4*)(Ah + g);
            *(uint4*)(sm + PR_AL + so) = *(const uint4*)(Al + g);
        }
        // Load B tile 64x64 (hi/lo)
        #pragma unroll
        for (int i = 0; i < 2; i++) {
            int u = tid + i * 256;
            int row = u >> 3, c8 = u & 7;
            uint32_t so = (uint32_t)(row * 72 + c8 * 8) * 2;
            size_t g = (size_t)(col0 + row) * DMODEL + kc0 + c8 * 8;
            *(uint4*)(sm + PR_BH + so) = *(const uint4*)(Bh + g);
            *(uint4*)(sm + PR_BL + so) = *(const uint4*)(Bl + g);
        }
        __syncthreads();

        #pragma unroll
        for (int ks = 0; ks < 4; ks++) {
            const int kk = ks * 16;
            uint32_t ah[2][4], al[2][4];
            #pragma unroll
            for (int mt = 0; mt < 2; mt++) {
                uint32_t ad = (uint32_t)((wm + mt * 16 + l16) * 72 + kk + ((lane >> 4) << 3)) * 2;
                ldmx4(ah[mt], sb + PR_AH + ad);
                ldmx4(al[mt], sb + PR_AL + ad);
            }
            uint32_t bh[4][2], bl[4][2];
            #pragma unroll
            for (int nt = 0; nt < 4; nt++) {
                uint32_t bd = (uint32_t)((wn + nt * 8 + (l16 & 7)) * 72 + kk + ((l16 >> 3) << 3)) * 2;
                ldmx2(bh[nt], sb + PR_BH + bd);
                ldmx2(bl[nt], sb + PR_BL + bd);
            }
            #pragma unroll
            for (int mt = 0; mt < 2; mt++)
                #pragma unroll
                for (int nt = 0; nt < 4; nt++) {
                    mma16816(acc[mt][nt], ah[mt], bh[nt]);
                    mma16816(acc[mt][nt], ah[mt], bl[nt]);
                    mma16816(acc[mt][nt], al[mt], bh[nt]);
                }
        }
        __syncthreads();
    }

    // Epilogue
    #pragma unroll
    for (int mt = 0; mt < 2; mt++)
        #pragma unroll
        for (int nt = 0; nt < 4; nt++) {
            int cg = col0 + wn + nt * 8 + (lane & 3) * 2;
            float b0 = bias[cg], b1 = bias[cg + 1];
            #pragma unroll
            for (int half = 0; half < 2; half++) {
                int r = row0 + wm + mt * 16 + half * 8 + (lane >> 2);
                float v0 = acc[mt][nt][half * 2]     + b0;
                float v1 = acc[mt][nt][half * 2 + 1] + b1;
                if (mode == 0) {
                    __nv_bfloat16 h0, l0, h1, l1;
                    bsplit(v0, h0, l0); bsplit(v1, h1, l1);
                    size_t idx = (size_t)r * DMODEL + cg;
                    *(uint32_t*)(Oh + idx) = bpack(h0, h1);
                    *(uint32_t*)(Ol + idx) = bpack(l0, l1);
                } else if (mode == 1) {
                    int s = r & (SEQ - 1), bb = r >> 12;
                    __nv_bfloat16 h0, l0, h1, l1;
                    bsplit(v0, h0, l0); bsplit(v1, h1, l1);
                    size_t i0 = ((size_t)((bb * NHEAD + (cg >> 6)) * HEADD + (cg & 63))) * SEQ + s;
                    size_t i1 = ((size_t)((bb * NHEAD + ((cg + 1) >> 6)) * HEADD + ((cg + 1) & 63))) * SEQ + s;
                    Oh[i0] = h0; Ol[i0] = l0;
                    Oh[i1] = h1; Ol[i1] = l1;
                } else {
                    Of[(size_t)r * DMODEL + cg]     = v0;
                    Of[(size_t)r * DMODEL + cg + 1] = v1;
                }
            }
        }
}

// ===========================================================================
// Attention via mma.sync (causal, no-max softmax).
// Grid (32, 8, 2), block 256 (8 warps). 128 queries/block, key tiles of 128.
// GEMM1 warps 4x2 (32q x 64key), GEMM2 warps 4x2 (32q x 32d).
// ===========================================================================
#define AT_QH 0
#define AT_QL 18432
#define AT_KH 36864
#define AT_KL 55296
#define AT_VH 73728
#define AT_VL 91136
#define AT_PH 108544
#define AT_PL 143360
#define AT_LRED 178176
#define AT_SMEM 179200

__global__ __launch_bounds__(256) void attn_mma_kernel(
    const __nv_bfloat16* __restrict__ Qh, const __nv_bfloat16* __restrict__ Ql,
    const __nv_bfloat16* __restrict__ Kh, const __nv_bfloat16* __restrict__ Kl,
    const __nv_bfloat16* __restrict__ Vth, const __nv_bfloat16* __restrict__ Vtl,
    __nv_bfloat16* __restrict__ Ah, __nv_bfloat16* __restrict__ Al)
{
    extern __shared__ __align__(16) char sm[];
    const uint32_t sb = smem_u32(sm);
    float* lred = (float*)(sm + AT_LRED);

    const int qt = blockIdx.x, h = blockIdx.y, b = blockIdx.z;
    const int q0 = qt * 128;
    const int tid = threadIdx.x;
    const int lane = tid & 31, wid = tid >> 5;
    const int wm  = (wid & 3) * 32;
    const int wn1 = (wid >> 2) * 64;   // GEMM1: key cols
    const int wn2 = (wid >> 2) * 32;   // GEMM2: d cols
    const int l16 = lane & 15;

    // Load Q tile 128x64 hi/lo
    #pragma unroll
    for (int i = 0; i < 4; i++) {
        int u = tid + i * 256;
        int row = u >> 3, c8 = u & 7;
        uint32_t so = (uint32_t)(row * 72 + c8 * 8) * 2;
        size_t g = (size_t)(b * SEQ + q0 + row) * DMODEL + h * HEADD + c8 * 8;
        *(uint4*)(sm + AT_QH + so) = *(const uint4*)(Qh + g);
        *(uint4*)(sm + AT_QL + so) = *(const uint4*)(Ql + g);
    }

    float o[2][4][4] = {};
    float ls[2][2] = {};

    for (int kt = 0; kt <= qt; kt++) {
        const int k0 = kt * 128;
        __syncthreads();   // protect K/V/P smem from previous iteration's readers

        // K tile 128x64 hi/lo
        #pragma unroll
        for (int i = 0; i < 4; i++) {
            int u = tid + i * 256;
            int row = u >> 3, c8 = u & 7;
            uint32_t so = (uint32_t)(row * 72 + c8 * 8) * 2;
            size_t g = (size_t)(b * SEQ + k0 + row) * DMODEL + h * HEADD + c8 * 8;
            *(uint4*)(sm + AT_KH + so) = *(const uint4*)(Kh + g);
            *(uint4*)(sm + AT_KL + so) = *(const uint4*)(Kl + g);
        }
        // Vt tile 64(d) x 128(keys) hi/lo
        #pragma unroll
        for (int i = 0; i < 4; i++) {
            int u = tid + i * 256;
            int d = u >> 4, c8 = u & 15;
            uint32_t so = (uint32_t)(d * 136 + c8 * 8) * 2;
            size_t g = ((size_t)((b * NHEAD + h) * HEADD + d)) * SEQ + k0 + c8 * 8;
            *(uint4*)(sm + AT_VH + so) = *(const uint4*)(Vth + g);
            *(uint4*)(sm + AT_VL + so) = *(const uint4*)(Vtl + g);
        }
        __syncthreads();

        // GEMM1: S[32q x 64key] per warp, K-dim = 64 (head dim)
        float s[2][8][4] = {};
        #pragma unroll
        for (int ks = 0; ks < 4; ks++) {
            const int kk = ks * 16;
            uint32_t qfh[2][4], qfl[2][4];
            #pragma unroll
            for (int mt = 0; mt < 2; mt++) {
                uint32_t ad = (uint32_t)((wm + mt * 16 + l16) * 72 + kk + ((lane >> 4) << 3)) * 2;
                ldmx4(qfh[mt], sb + AT_QH + ad);
                ldmx4(qfl[mt], sb + AT_QL + ad);
            }
            #pragma unroll
            for (int nt = 0; nt < 8; nt++) {
                uint32_t kfh[2], kfl[2];
                uint32_t bd = (uint32_t)((wn1 + nt * 8 + (l16 & 7)) * 72 + kk + ((l16 >> 3) << 3)) * 2;
                ldmx2(kfh, sb + AT_KH + bd);
                ldmx2(kfl, sb + AT_KL + bd);
                #pragma unroll
                for (int mt = 0; mt < 2; mt++) {
                    mma16816(s[mt][nt], qfh[mt], kfh);
                    mma16816(s[mt][nt], qfh[mt], kfl);
                    mma16816(s[mt][nt], qfl[mt], kfh);
                }
            }
        }

        // Softmax numerator (no max subtraction) + causal mask + P -> smem
        const bool diag = (kt == qt);
        #pragma unroll
        for (int mt = 0; mt < 2; mt++)
            #pragma unroll
            for (int nt = 0; nt < 8; nt++) {
                int cg = wn1 + nt * 8 + (lane & 3) * 2;
                #pragma unroll
                for (int half = 0; half < 2; half++) {
                    int r = wm + mt * 16 + half * 8 + (lane >> 2);
                    float p0 = __expf(s[mt][nt][half * 2]     * 0.125f);
                    float p1 = __expf(s[mt][nt][half * 2 + 1] * 0.125f);
                    if (diag) {
                        if (cg > r)     p0 = 0.0f;
                        if (cg + 1 > r) p1 = 0.0f;
                    }
                    ls[mt][half] += p0 + p1;
                    __nv_bfloat16 h0, l0, h1, l1;
                    bsplit(p0, h0, l0); bsplit(p1, h1, l1);
                    uint32_t so = (uint32_t)(r * 136 + cg) * 2;
                    *(uint32_t*)(sm + AT_PH + so) = bpack(h0, h1);
                    *(uint32_t*)(sm + AT_PL + so) = bpack(l0, l1);
                }
            }
        __syncthreads();

        // GEMM2: O[32q x 32d] += P[32q x 128] Vt[32d x 128]^T
        #pragma unroll
        for (int ks = 0; ks < 8; ks++) {
            const int kk = ks * 16;
            uint32_t pfh[2][4], pfl[2][4];
            #pragma unroll
            for (int mt = 0; mt < 2; mt++) {
                uint32_t ad = (uint32_t)((wm + mt * 16 + l16) * 136 + kk + ((lane >> 4) << 3)) * 2;
                ldmx4(pfh[mt], sb + AT_PH + ad);
                ldmx4(pfl[mt], sb + AT_PL + ad);
            }
            #pragma unroll
            for (int nt = 0; nt < 4; nt++) {
                uint32_t vfh[2], vfl[2];
                uint32_t bd = (uint32_t)((wn2 + nt * 8 + (l16 & 7)) * 136 + kk + ((l16 >> 3) << 3)) * 2;
                ldmx2(vfh, sb + AT_VH + bd);
                ldmx2(vfl, sb + AT_VL + bd);
                #pragma unroll
                for (int mt = 0; mt < 2; mt++) {
                    mma16816(o[mt][nt], pfh[mt], vfh);
                    mma16816(o[mt][nt], pfh[mt], vfl);
                    mma16816(o[mt][nt], pfl[mt], vfh);
                }
            }
        }
    }

    // Row-sum reduce: quad shuffle then cross-warp (key halves) via smem
    #pragma unroll
    for (int mt = 0; mt < 2; mt++)
        #pragma unroll
        for (int half = 0; half < 2; half++) {
            float v = ls[mt][half];
            v += __shfl_xor_sync(0xFFFFFFFFu, v, 1);
            v += __shfl_xor_sync(0xFFFFFFFFu, v, 2);
            if ((lane & 3) == 0) {
                int r = wm + mt * 16 + half * 8 + (lane >> 2);
                lred[(wid >> 2) * 128 + r] = v;
            }
        }
    __syncthreads();

    // Epilogue: O / l -> bf16 hi/lo at [b][q][h*64+d]
    #pragma unroll
    for (int mt = 0; mt < 2; mt++)
        #pragma unroll
        for (int nt = 0; nt < 4; nt++) {
            int dd = wn2 + nt * 8 + (lane & 3) * 2;
            #pragma unroll
            for (int half = 0; half < 2; half++) {
                int r = wm + mt * 16 + half * 8 + (lane >> 2);
                float linv = 1.0f / (lred[r] + lred[128 + r]);
                float v0 = o[mt][nt][half * 2]     * linv;
                float v1 = o[mt][nt][half * 2 + 1] * linv;
                __nv_bfloat16 h0, l0, h1, l1;
                bsplit(v0, h0, l0); bsplit(v1, h1, l1);
                size_t idx = (size_t)(b * SEQ + q0 + r) * DMODEL + h * HEADD + dd;
                *(uint32_t*)(Ah + idx) = bpack(h0, h1);
                *(uint32_t*)(Al + idx) = bpack(l0, l1);
            }
        }
}

// ===========================================================================
// Launch
// ===========================================================================
extern "C" void kernel_launch(void* const* d_in, const int* in_sizes, int n_in,
                              void* d_out, int out_size)
{
    const float* x  = (const float*)d_in[0];
    const float* Wq = (const float*)d_in[1];
    const float* bq = (const float*)d_in[2];
    const float* Wk = (const float*)d_in[3];
    const float* bk = (const float*)d_in[4];
    const float* Wv = (const float*)d_in[5];
    const float* bv = (const float*)d_in[6];
    const float* Wo = (const float*)d_in[7];
    const float* bo = (const float*)d_in[8];
    float* out = (float*)d_out;

    __nv_bfloat16 *xh, *xl, *wth, *wtl, *qh, *ql, *kh, *kl, *vth, *vtl, *ah, *al;
    cudaGetSymbolAddress((void**)&xh,  g_xh);
    cudaGetSymbolAddress((void**)&xl,  g_xl);
    cudaGetSymbolAddress((void**)&wth, g_wth);
    cudaGetSymbolAddress((void**)&wtl, g_wtl);
    cudaGetSymbolAddress((void**)&qh,  g_qh);
    cudaGetSymbolAddress((void**)&ql,  g_ql);
    cudaGetSymbolAddress((void**)&kh,  g_kh);
    cudaGetSymbolAddress((void**)&kl,  g_kl);
    cudaGetSymbolAddress((void**)&vth, g_vth);
    cudaGetSymbolAddress((void**)&vtl, g_vtl);
    cudaGetSymbolAddress((void**)&ah,  g_ah);
    cudaGetSymbolAddress((void**)&al,  g_al);

    cudaFuncSetAttribute(gemm_mma_kernel,
                         cudaFuncAttributeMaxDynamicSharedMemorySize, PR_SMEM);
    cudaFuncSetAttribute(attn_mma_kernel,
                         cudaFuncAttributeMaxDynamicSharedMemorySize, AT_SMEM);

    const int WSZ = DMODEL * DMODEL;

    split_kernel<<<2048, 256>>>(x, xh, xl, MTOT * DMODEL);
    dim3 wb(32, 8), wg(16, 16);
    wsplit_kernel<<<wg, wb>>>(Wq, wth + 0 * WSZ, wtl + 0 * WSZ);
    wsplit_kernel<<<wg, wb>>>(Wk, wth + 1 * WSZ, wtl + 1 * WSZ);
    wsplit_kernel<<<wg, wb>>>(Wv, wth + 2 * WSZ, wtl + 2 * WSZ);
    wsplit_kernel<<<wg, wb>>>(Wo, wth + 3 * WSZ, wtl + 3 * WSZ);

    dim3 gg(DMODEL / 64, MTOT / 128);   // (8, 64)
    gemm_mma_kernel<<<gg, 256, PR_SMEM>>>(xh, xl, wth + 0 * WSZ, wtl + 0 * WSZ,
                                          bq, 0, qh, ql, nullptr);
    gemm_mma_kernel<<<gg, 256, PR_SMEM>>>(xh, xl, wth + 1 * WSZ, wtl + 1 * WSZ,
                                          bk, 0, kh, kl, nullptr);
    gemm_mma_kernel<<<gg, 256, PR_SMEM>>>(xh, xl, wth + 2 * WSZ, wtl + 2 * WSZ,
                                          bv, 1, vth, vtl, nullptr);

    dim3 ag(SEQ / 128, NHEAD, BATCH);   // (32, 8, 2)
    attn_mma_kernel<<<ag, 256, AT_SMEM>>>(qh, ql, kh, kl, vth, vtl, ah, al);

    gemm_mma_kernel<<<gg, 256, PR_SMEM>>>(ah, al, wth + 3 * WSZ, wtl + 3 * WSZ,
                                          bo, 2, nullptr, nullptr, out);
}

// round 5
// speedup vs baseline: 3.5439x; 1.1708x over previous
#include <cuda_runtime.h>
#include <cuda_bf16.h>
#include <cstdint>

// ===========================================================================
// Problem: B=2, S=4096, D=512, H=8, HD=64
// ===========================================================================
#define BATCH 2
#define SEQ   4096
#define DMODEL 512
#define NHEAD 8
#define HEADD 64
#define MTOT  (BATCH * SEQ)   // 8192

// ===========================================================================
// Helpers
// ===========================================================================
__device__ __forceinline__ uint32_t smem_u32(const void* p) {
    uint32_t a;
    asm("{ .reg .u64 t; cvta.to.shared.u64 t, %1; cvt.u32.u64 %0, t; }"
        : "=r"(a) : "l"(p));
    return a;
}

__device__ __forceinline__ void ldmx4(uint32_t r[4], uint32_t a) {
    asm volatile("ldmatrix.sync.aligned.m8n8.x4.shared.b16 {%0,%1,%2,%3}, [%4];"
                 : "=r"(r[0]), "=r"(r[1]), "=r"(r[2]), "=r"(r[3]) : "r"(a));
}
__device__ __forceinline__ void ldmx2(uint32_t r[2], uint32_t a) {
    asm volatile("ldmatrix.sync.aligned.m8n8.x2.shared.b16 {%0,%1}, [%2];"
                 : "=r"(r[0]), "=r"(r[1]) : "r"(a));
}
// D += A * B  (m16n8k16, bf16 in, f32 accum)
__device__ __forceinline__ void mma16816(float (&c)[4], const uint32_t (&a)[4],
                                         const uint32_t (&b)[2]) {
    asm volatile(
        "mma.sync.aligned.m16n8k16.row.col.f32.bf16.bf16.f32 "
        "{%0,%1,%2,%3}, {%4,%5,%6,%7}, {%8,%9}, {%0,%1,%2,%3};"
        : "+f"(c[0]), "+f"(c[1]), "+f"(c[2]), "+f"(c[3])
        : "r"(a[0]), "r"(a[1]), "r"(a[2]), "r"(a[3]), "r"(b[0]), "r"(b[1]));
}
__device__ __forceinline__ void mma2(float (&c)[4], const uint32_t (&a)[4],
                                     uint32_t b0, uint32_t b1) {
    asm volatile(
        "mma.sync.aligned.m16n8k16.row.col.f32.bf16.bf16.f32 "
        "{%0,%1,%2,%3}, {%4,%5,%6,%7}, {%8,%9}, {%0,%1,%2,%3};"
        : "+f"(c[0]), "+f"(c[1]), "+f"(c[2]), "+f"(c[3])
        : "r"(a[0]), "r"(a[1]), "r"(a[2]), "r"(a[3]), "r"(b0), "r"(b1));
}

__device__ __forceinline__ void bsplit(float v, __nv_bfloat16& h, __nv_bfloat16& l) {
    h = __float2bfloat16(v);
    l = __float2bfloat16(v - __bfloat162float(h));
}
__device__ __forceinline__ uint32_t bpack(__nv_bfloat16 a, __nv_bfloat16 b) {
    return (uint32_t)__bfloat16_as_ushort(a) |
           ((uint32_t)__bfloat16_as_ushort(b) << 16);
}
// packed = {hi: cvt(h), lo: cvt(l)}
__device__ __forceinline__ uint32_t cvt2bf(float h, float l) {
    uint32_t r;
    asm("cvt.rn.bf16x2.f32 %0, %1, %2;" : "=r"(r) : "f"(h), "f"(l));
    return r;
}

__device__ __forceinline__ void cpa16(uint32_t s, const void* g) {
    asm volatile("cp.async.cg.shared.global [%0], [%1], 16;" :: "r"(s), "l"(g));
}
#define CP_COMMIT() asm volatile("cp.async.commit_group;" ::: "memory")
#define CP_WAIT1()  asm volatile("cp.async.wait_group 1;" ::: "memory")

// ===========================================================================
// Scratch (device globals — allocation-free)
// ===========================================================================
__device__ __nv_bfloat16 g_xh[MTOT * DMODEL], g_xl[MTOT * DMODEL];
__device__ __nv_bfloat16 g_wth[4 * DMODEL * DMODEL], g_wtl[4 * DMODEL * DMODEL];
__device__ __nv_bfloat16 g_qh[MTOT * DMODEL], g_ql[MTOT * DMODEL];
__device__ __nv_bfloat16 g_kh[MTOT * DMODEL], g_kl[MTOT * DMODEL];
__device__ __nv_bfloat16 g_vth[MTOT * DMODEL], g_vtl[MTOT * DMODEL]; // [(b*8+h)*64+d][4096]
__device__ __nv_bfloat16 g_ah[MTOT * DMODEL], g_al[MTOT * DMODEL];

// ===========================================================================
// fp32 -> bf16 hi/lo split kernels
// ===========================================================================
__global__ void split_kernel(const float* __restrict__ x,
                             __nv_bfloat16* __restrict__ h,
                             __nv_bfloat16* __restrict__ l, int n) {
    for (int i = blockIdx.x * blockDim.x + threadIdx.x; i < n;
         i += gridDim.x * blockDim.x) {
        __nv_bfloat16 a, b;
        bsplit(x[i], a, b);
        h[i] = a; l[i] = b;
    }
}

__global__ void wsplit_kernel(const float* __restrict__ W,
                              __nv_bfloat16* __restrict__ th,
                              __nv_bfloat16* __restrict__ tl) {
    __shared__ float t[32][33];
    int bx = blockIdx.x * 32, by = blockIdx.y * 32;
    int tx = threadIdx.x, ty = threadIdx.y;
    #pragma unroll
    for (int i = 0; i < 4; i++)
        t[ty + i * 8][tx] = W[(size_t)(by + ty + i * 8) * DMODEL + bx + tx];
    __syncthreads();
    #pragma unroll
    for (int i = 0; i < 4; i++) {
        float v = t[tx][ty + i * 8];
        __nv_bfloat16 h, l;
        bsplit(v, h, l);
        size_t idx = (size_t)(bx + ty + i * 8) * DMODEL + by + tx;
        th[idx] = h; tl[idx] = l;
    }
}

// ===========================================================================
// Projection GEMM via mma.sync (unchanged from round 4 — known good)
// ===========================================================================
#define PR_AH 0
#define PR_AL 18432
#define PR_BH 36864
#define PR_BL 46080
#define PR_SMEM 55296

__global__ __launch_bounds__(256) void gemm_mma_kernel(
    const __nv_bfloat16* __restrict__ Ah, const __nv_bfloat16* __restrict__ Al,
    const __nv_bfloat16* __restrict__ Bh, const __nv_bfloat16* __restrict__ Bl,
    const float* __restrict__ bias, int mode,
    __nv_bfloat16* __restrict__ Oh, __nv_bfloat16* __restrict__ Ol,
    float* __restrict__ Of)
{
    extern __shared__ __align__(16) char sm[];
    const uint32_t sb = smem_u32(sm);
    const int tid = threadIdx.x;
    const int lane = tid & 31, wid = tid >> 5;
    const int wm = (wid & 3) * 32, wn = (wid >> 2) * 32;
    const int col0 = blockIdx.x * 64;
    const int row0 = blockIdx.y * 128;
    const int l16 = lane & 15;

    float acc[2][4][4] = {};

    for (int chunk = 0; chunk < 8; chunk++) {
        const int kc0 = chunk * 64;
        #pragma unroll
        for (int i = 0; i < 4; i++) {
            int u = tid + i * 256;
            int row = u >> 3, c8 = u & 7;
            uint32_t so = (uint32_t)(row * 72 + c8 * 8) * 2;
            size_t g = (size_t)(row0 + row) * DMODEL + kc0 + c8 * 8;
            *(uint4*)(sm + PR_AH + so) = *(const uint4*)(Ah + g);
            *(uint4*)(sm + PR_AL + so) = *(const uint4*)(Al + g);
        }
        #pragma unroll
        for (int i = 0; i < 2; i++) {
            int u = tid + i * 256;
            int row = u >> 3, c8 = u & 7;
            uint32_t so = (uint32_t)(row * 72 + c8 * 8) * 2;
            size_t g = (size_t)(col0 + row) * DMODEL + kc0 + c8 * 8;
            *(uint4*)(sm + PR_BH + so) = *(const uint4*)(Bh + g);
            *(uint4*)(sm + PR_BL + so) = *(const uint4*)(Bl + g);
        }
        __syncthreads();

        #pragma unroll
        for (int ks = 0; ks < 4; ks++) {
            const int kk = ks * 16;
            uint32_t ah[2][4], al[2][4];
            #pragma unroll
            for (int mt = 0; mt < 2; mt++) {
                uint32_t ad = (uint32_t)((wm + mt * 16 + l16) * 72 + kk + ((lane >> 4) << 3)) * 2;
                ldmx4(ah[mt], sb + PR_AH + ad);
                ldmx4(al[mt], sb + PR_AL + ad);
            }
            uint32_t bh[4][2], bl[4][2];
            #pragma unroll
            for (int nt = 0; nt < 4; nt++) {
                uint32_t bd = (uint32_t)((wn + nt * 8 + (l16 & 7)) * 72 + kk + ((l16 >> 3) << 3)) * 2;
                ldmx2(bh[nt], sb + PR_BH + bd);
                ldmx2(bl[nt], sb + PR_BL + bd);
            }
            #pragma unroll
            for (int mt = 0; mt < 2; mt++)
                #pragma unroll
                for (int nt = 0; nt < 4; nt++) {
                    mma16816(acc[mt][nt], ah[mt], bh[nt]);
                    mma16816(acc[mt][nt], ah[mt], bl[nt]);
                    mma16816(acc[mt][nt], al[mt], bh[nt]);
                }
        }
        __syncthreads();
    }

    #pragma unroll
    for (int mt = 0; mt < 2; mt++)
        #pragma unroll
        for (int nt = 0; nt < 4; nt++) {
            int cg = col0 + wn + nt * 8 + (lane & 3) * 2;
            float b0 = bias[cg], b1 = bias[cg + 1];
            #pragma unroll
            for (int half = 0; half < 2; half++) {
                int r = row0 + wm + mt * 16 + half * 8 + (lane >> 2);
                float v0 = acc[mt][nt][half * 2]     + b0;
                float v1 = acc[mt][nt][half * 2 + 1] + b1;
                if (mode == 0) {
                    __nv_bfloat16 h0, l0, h1, l1;
                    bsplit(v0, h0, l0); bsplit(v1, h1, l1);
                    size_t idx = (size_t)r * DMODEL + cg;
                    *(uint32_t*)(Oh + idx) = bpack(h0, h1);
                    *(uint32_t*)(Ol + idx) = bpack(l0, l1);
                } else if (mode == 1) {
                    int s = r & (SEQ - 1), bb = r >> 12;
                    __nv_bfloat16 h0, l0, h1, l1;
                    bsplit(v0, h0, l0); bsplit(v1, h1, l1);
                    size_t i0 = ((size_t)((bb * NHEAD + (cg >> 6)) * HEADD + (cg & 63))) * SEQ + s;
                    size_t i1 = ((size_t)((bb * NHEAD + ((cg + 1) >> 6)) * HEADD + ((cg + 1) & 63))) * SEQ + s;
                    Oh[i0] = h0; Ol[i0] = l0;
                    Oh[i1] = h1; Ol[i1] = l1;
                } else {
                    Of[(size_t)r * DMODEL + cg]     = v0;
                    Of[(size_t)r * DMODEL + cg + 1] = v1;
                }
            }
        }
}

// ===========================================================================
// Attention v2: register-resident P, cp.async double-buffered K/V,
// ldmatrix x4 B-operands, per-quad row sums. 8 warps x 16 q-rows.
// smem: two buffers of [KH 18432 | KL 18432 | VH 17408 | VL 17408] = 71680.
// Q (hi 18432 + lo 18432) aliases buf0 during prologue only.
// ===========================================================================
#define AB_KH 0
#define AB_KL 18432
#define AB_VH 36864
#define AB_VL 54272
#define AB_SZ 71680
#define AT2_SMEM (2 * AB_SZ)   // 143360

struct AttnPtrs {
    const __nv_bfloat16 *Kh, *Kl, *Vth, *Vtl;
};

__global__ __launch_bounds__(256) void attn_mma2_kernel(
    const __nv_bfloat16* __restrict__ Qh, const __nv_bfloat16* __restrict__ Ql,
    const __nv_bfloat16* __restrict__ Kh, const __nv_bfloat16* __restrict__ Kl,
    const __nv_bfloat16* __restrict__ Vth, const __nv_bfloat16* __restrict__ Vtl,
    __nv_bfloat16* __restrict__ Ah, __nv_bfloat16* __restrict__ Al)
{
    extern __shared__ __align__(16) char sm[];
    const uint32_t sb = smem_u32(sm);

    const int qt = (SEQ / 128 - 1) - blockIdx.x;   // long blocks first
    const int h = blockIdx.y, b = blockIdx.z;
    const int q0 = qt * 128;
    const int tid = threadIdx.x;
    const int lane = tid & 31, wid = tid >> 5;
    const int r0 = wid * 16;
    const int l16 = lane & 15;

    const size_t kbase = (size_t)(b * SEQ) * DMODEL + h * HEADD;
    const size_t vbase = ((size_t)((b * NHEAD + h) * HEADD)) * SEQ;

    // ---- Prologue: Q tile -> smem (aliases buf0), extract fragments ----
    #pragma unroll
    for (int i = 0; i < 4; i++) {
        int u = tid + i * 256;
        int row = u >> 3, c8 = u & 7;
        uint32_t so = (uint32_t)(row * 144 + c8 * 16);
        size_t g = kbase + (size_t)(q0 + row) * DMODEL + c8 * 8;
        *(uint4*)(sm + so)         = *(const uint4*)(Qh + g);
        *(uint4*)(sm + 18432 + so) = *(const uint4*)(Ql + g);
    }
    __syncthreads();

    uint32_t qfh[4][4], qfl[4][4];
    #pragma unroll
    for (int ks = 0; ks < 4; ks++) {
        uint32_t ad = (uint32_t)((r0 + l16) * 72 + ks * 16 + ((lane >> 4) << 3)) * 2;
        ldmx4(qfh[ks], sb + ad);
        ldmx4(qfl[ks], sb + 18432 + ad);
    }
    __syncthreads();   // done with Q smem; buffers may be overwritten

    // ---- Prefetch tiles 0 and 1 ----
    {
        // tile 0 -> buf0
        #pragma unroll
        for (int i = 0; i < 4; i++) {
            int u = tid + i * 256;
            int row = u >> 3, c8 = u & 7;
            uint32_t so = (uint32_t)(row * 144 + c8 * 16);
            const __nv_bfloat16* g = Kh + kbase + (size_t)row * DMODEL + c8 * 8;
            const __nv_bfloat16* gl = Kl + kbase + (size_t)row * DMODEL + c8 * 8;
            cpa16(sb + AB_KH + so, g);
            cpa16(sb + AB_KL + so, gl);
        }
        #pragma unroll
        for (int i = 0; i < 4; i++) {
            int u = tid + i * 256;
            int d = u >> 4, c16 = u & 15;
            uint32_t so = (uint32_t)(d * 272 + c16 * 16);
            cpa16(sb + AB_VH + so, Vth + vbase + (size_t)d * SEQ + c16 * 8);
            cpa16(sb + AB_VL + so, Vtl + vbase + (size_t)d * SEQ + c16 * 8);
        }
        CP_COMMIT();
        if (qt >= 1) {
            const int k0 = 128;
            #pragma unroll
            for (int i = 0; i < 4; i++) {
                int u = tid + i * 256;
                int row = u >> 3, c8 = u & 7;
                uint32_t so = (uint32_t)(row * 144 + c8 * 16);
                cpa16(sb + AB_SZ + AB_KH + so, Kh + kbase + (size_t)(k0 + row) * DMODEL + c8 * 8);
                cpa16(sb + AB_SZ + AB_KL + so, Kl + kbase + (size_t)(k0 + row) * DMODEL + c8 * 8);
            }
            #pragma unroll
            for (int i = 0; i < 4; i++) {
                int u = tid + i * 256;
                int d = u >> 4, c16 = u & 15;
                uint32_t so = (uint32_t)(d * 272 + c16 * 16);
                cpa16(sb + AB_SZ + AB_VH + so, Vth + vbase + (size_t)d * SEQ + k0 + c16 * 8);
                cpa16(sb + AB_SZ + AB_VL + so, Vtl + vbase + (size_t)d * SEQ + k0 + c16 * 8);
            }
        }
        CP_COMMIT();
    }

    float o[8][4] = {};
    float lsA = 0.0f, lsB = 0.0f;
    const int rA = r0 + (lane >> 2);
    const int rB = rA + 8;

    for (int kt = 0; kt <= qt; kt++) {
        const uint32_t buf = sb + (uint32_t)(kt & 1) * AB_SZ;
        CP_WAIT1();
        __syncthreads();

        // --- GEMM1: S[16 x 128] = Q Kt ---
        float s[16][4];
        #pragma unroll
        for (int nt = 0; nt < 16; nt++)
            #pragma unroll
            for (int j = 0; j < 4; j++) s[nt][j] = 0.0f;

        #pragma unroll
        for (int ks = 0; ks < 4; ks++) {
            const int kk = ks * 16;
            #pragma unroll
            for (int np = 0; np < 8; np++) {
                uint32_t bh[4], bl[4];
                uint32_t ad = (uint32_t)((np * 16 + (lane & 7) + ((lane >> 4) << 3)) * 72
                                         + kk + (((lane >> 3) & 1) << 3)) * 2;
                ldmx4(bh, buf + AB_KH + ad);
                ldmx4(bl, buf + AB_KL + ad);
                mma2(s[2 * np],     qfh[ks], bh[0], bh[1]);
                mma2(s[2 * np],     qfh[ks], bl[0], bl[1]);
                mma2(s[2 * np],     qfl[ks], bh[0], bh[1]);
                mma2(s[2 * np + 1], qfh[ks], bh[2], bh[3]);
                mma2(s[2 * np + 1], qfh[ks], bl[2], bl[3]);
                mma2(s[2 * np + 1], qfl[ks], bh[2], bh[3]);
            }
        }

        // --- Softmax numerator (no-max) + causal mask + split -> P frags ---
        const bool diag = (kt == qt);
        uint32_t ph[16][2], pl[16][2];
        #pragma unroll
        for (int nt = 0; nt < 16; nt++) {
            const int cg = nt * 8 + (lane & 3) * 2;
            float p0 = __expf(s[nt][0] * 0.125f);
            float p1 = __expf(s[nt][1] * 0.125f);
            float p2 = __expf(s[nt][2] * 0.125f);
            float p3 = __expf(s[nt][3] * 0.125f);
            if (diag) {
                if (cg > rA)     p0 = 0.0f;
                if (cg + 1 > rA) p1 = 0.0f;
                if (cg > rB)     p2 = 0.0f;
                if (cg + 1 > rB) p3 = 0.0f;
            }
            lsA += p0 + p1;
            lsB += p2 + p3;
            uint32_t h01 = cvt2bf(p1, p0);
            uint32_t h23 = cvt2bf(p3, p2);
            ph[nt][0] = h01; ph[nt][1] = h23;
            float f0 = __uint_as_float(h01 << 16);
            float f1 = __uint_as_float(h01 & 0xFFFF0000u);
            float f2 = __uint_as_float(h23 << 16);
            float f3 = __uint_as_float(h23 & 0xFFFF0000u);
            pl[nt][0] = cvt2bf(p1 - f1, p0 - f0);
            pl[nt][1] = cvt2bf(p3 - f3, p2 - f2);
        }

        // --- GEMM2: O[16 x 64] += P V ---
        #pragma unroll
        for (int kc = 0; kc < 8; kc++) {
            uint32_t pah[4] = {ph[2 * kc][0], ph[2 * kc][1],
                               ph[2 * kc + 1][0], ph[2 * kc + 1][1]};
            uint32_t pal[4] = {pl[2 * kc][0], pl[2 * kc][1],
                               pl[2 * kc + 1][0], pl[2 * kc + 1][1]};
            #pragma unroll
            for (int np = 0; np < 4; np++) {
                uint32_t vh[4], vl[4];
                uint32_t ad = (uint32_t)((np * 16 + (lane & 7) + ((lane >> 4) << 3)) * 136
                                         + kc * 16 + (((lane >> 3) & 1) << 3)) * 2;
                ldmx4(vh, buf + AB_VH + ad);
                ldmx4(vl, buf + AB_VL + ad);
                mma2(o[2 * np],     pah, vh[0], vh[1]);
                mma2(o[2 * np],     pah, vl[0], vl[1]);
                mma2(o[2 * np],     pal, vh[0], vh[1]);
                mma2(o[2 * np + 1], pah, vh[2], vh[3]);
                mma2(o[2 * np + 1], pah, vl[2], vl[3]);
                mma2(o[2 * np + 1], pal, vh[2], vh[3]);
            }
        }

        __syncthreads();   // all warps done reading this buffer

        // --- Prefetch tile kt+2 into this buffer ---
        if (kt + 2 <= qt) {
            const int k0 = (kt + 2) * 128;
            #pragma unroll
            for (int i = 0; i < 4; i++) {
                int u = tid + i * 256;
                int row = u >> 3, c8 = u & 7;
                uint32_t so = (uint32_t)(row * 144 + c8 * 16);
                cpa16(buf + AB_KH + so, Kh + kbase + (size_t)(k0 + row) * DMODEL + c8 * 8);
                cpa16(buf + AB_KL + so, Kl + kbase + (size_t)(k0 + row) * DMODEL + c8 * 8);
            }
            #pragma unroll
            for (int i = 0; i < 4; i++) {
                int u = tid + i * 256;
                int d = u >> 4, c16 = u & 15;
                uint32_t so = (uint32_t)(d * 272 + c16 * 16);
                cpa16(buf + AB_VH + so, Vth + vbase + (size_t)d * SEQ + k0 + c16 * 8);
                cpa16(buf + AB_VL + so, Vtl + vbase + (size_t)d * SEQ + k0 + c16 * 8);
            }
        }
        CP_COMMIT();
    }

    // --- Row sums: reduce across the 4 column-owner lanes (quad) ---
    lsA += __shfl_xor_sync(0xFFFFFFFFu, lsA, 1);
    lsA += __shfl_xor_sync(0xFFFFFFFFu, lsA, 2);
    lsB += __shfl_xor_sync(0xFFFFFFFFu, lsB, 1);
    lsB += __shfl_xor_sync(0xFFFFFFFFu, lsB, 2);
    const float liA = 1.0f / lsA;
    const float liB = 1.0f / lsB;

    // --- Epilogue: O / l -> bf16 hi/lo at [b][q][h*64+d] ---
    #pragma unroll
    for (int nt = 0; nt < 8; nt++) {
        const int dd = nt * 8 + (lane & 3) * 2;
        float v0 = o[nt][0] * liA, v1 = o[nt][1] * liA;
        float v2 = o[nt][2] * liB, v3 = o[nt][3] * liB;
        __nv_bfloat16 h0, l0, h1, l1;
        bsplit(v0, h0, l0); bsplit(v1, h1, l1);
        size_t iA = (size_t)(b * SEQ + q0 + rA) * DMODEL + h * HEADD + dd;
        *(uint32_t*)(Ah + iA) = bpack(h0, h1);
        *(uint32_t*)(Al + iA) = bpack(l0, l1);
        bsplit(v2, h0, l0); bsplit(v3, h1, l1);
        size_t iB = (size_t)(b * SEQ + q0 + rB) * DMODEL + h * HEADD + dd;
        *(uint32_t*)(Ah + iB) = bpack(h0, h1);
        *(uint32_t*)(Al + iB) = bpack(l0, l1);
    }
}

// ===========================================================================
// Launch
// ===========================================================================
extern "C" void kernel_launch(void* const* d_in, const int* in_sizes, int n_in,
                              void* d_out, int out_size)
{
    const float* x  = (const float*)d_in[0];
    const float* Wq = (const float*)d_in[1];
    const float* bq = (const float*)d_in[2];
    const float* Wk = (const float*)d_in[3];
    const float* bk = (const float*)d_in[4];
    const float* Wv = (const float*)d_in[5];
    const float* bv = (const float*)d_in[6];
    const float* Wo = (const float*)d_in[7];
    const float* bo = (const float*)d_in[8];
    float* out = (float*)d_out;

    __nv_bfloat16 *xh, *xl, *wth, *wtl, *qh, *ql, *kh, *kl, *vth, *vtl, *ah, *al;
    cudaGetSymbolAddress((void**)&xh,  g_xh);
    cudaGetSymbolAddress((void**)&xl,  g_xl);
    cudaGetSymbolAddress((void**)&wth, g_wth);
    cudaGetSymbolAddress((void**)&wtl, g_wtl);
    cudaGetSymbolAddress((void**)&qh,  g_qh);
    cudaGetSymbolAddress((void**)&ql,  g_ql);
    cudaGetSymbolAddress((void**)&kh,  g_kh);
    cudaGetSymbolAddress((void**)&kl,  g_kl);
    cudaGetSymbolAddress((void**)&vth, g_vth);
    cudaGetSymbolAddress((void**)&vtl, g_vtl);
    cudaGetSymbolAddress((void**)&ah,  g_ah);
    cudaGetSymbolAddress((void**)&al,  g_al);

    cudaFuncSetAttribute(gemm_mma_kernel,
                         cudaFuncAttributeMaxDynamicSharedMemorySize, PR_SMEM);
    cudaFuncSetAttribute(attn_mma2_kernel,
                         cudaFuncAttributeMaxDynamicSharedMemorySize, AT2_SMEM);

    const int WSZ = DMODEL * DMODEL;

    split_kernel<<<2048, 256>>>(x, xh, xl, MTOT * DMODEL);
    dim3 wb(32, 8), wg(16, 16);
    wsplit_kernel<<<wg, wb>>>(Wq, wth + 0 * WSZ, wtl + 0 * WSZ);
    wsplit_kernel<<<wg, wb>>>(Wk, wth + 1 * WSZ, wtl + 1 * WSZ);
    wsplit_kernel<<<wg, wb>>>(Wv, wth + 2 * WSZ, wtl + 2 * WSZ);
    wsplit_kernel<<<wg, wb>>>(Wo, wth + 3 * WSZ, wtl + 3 * WSZ);

    dim3 gg(DMODEL / 64, MTOT / 128);   // (8, 64)
    gemm_mma_kernel<<<gg, 256, PR_SMEM>>>(xh, xl, wth + 0 * WSZ, wtl + 0 * WSZ,
                                          bq, 0, qh, ql, nullptr);
    gemm_mma_kernel<<<gg, 256, PR_SMEM>>>(xh, xl, wth + 1 * WSZ, wtl + 1 * WSZ,
                                          bk, 0, kh, kl, nullptr);
    gemm_mma_kernel<<<gg, 256, PR_SMEM>>>(xh, xl, wth + 2 * WSZ, wtl + 2 * WSZ,
                                          bv, 1, vth, vtl, nullptr);

    dim3 ag(SEQ / 128, NHEAD, BATCH);   // (32, 8, 2)
    attn_mma2_kernel<<<ag, 256, AT2_SMEM>>>(qh, ql, kh, kl, vth, vtl, ah, al);

    gemm_mma_kernel<<<gg, 256, PR_SMEM>>>(ah, al, wth + 3 * WSZ, wtl + 3 * WSZ,
                                          bo, 2, nullptr, nullptr, out);
}

// round 7
// speedup vs baseline: 3.7236x; 1.0507x over previous
#include <cuda_runtime.h>
#include <cuda_bf16.h>
#include <cstdint>

// ===========================================================================
// Problem: B=2, S=4096, D=512, H=8, HD=64
// ===========================================================================
#define BATCH 2
#define SEQ   4096
#define DMODEL 512
#define NHEAD 8
#define HEADD 64
#define MTOT  (BATCH * SEQ)   // 8192
#define QSCALE 0.18033688011f  // 0.125 * log2(e)

// ===========================================================================
// Helpers
// ===========================================================================
__device__ __forceinline__ uint32_t smem_u32(const void* p) {
    uint32_t a;
    asm("{ .reg .u64 t; cvta.to.shared.u64 t, %1; cvt.u32.u64 %0, t; }"
        : "=r"(a) : "l"(p));
    return a;
}
__device__ __forceinline__ void ldmx4(uint32_t r[4], uint32_t a) {
    asm volatile("ldmatrix.sync.aligned.m8n8.x4.shared.b16 {%0,%1,%2,%3}, [%4];"
                 : "=r"(r[0]), "=r"(r[1]), "=r"(r[2]), "=r"(r[3]) : "r"(a));
}
__device__ __forceinline__ void mma2(float (&c)[4], const uint32_t (&a)[4],
                                     uint32_t b0, uint32_t b1) {
    asm volatile(
        "mma.sync.aligned.m16n8k16.row.col.f32.bf16.bf16.f32 "
        "{%0,%1,%2,%3}, {%4,%5,%6,%7}, {%8,%9}, {%0,%1,%2,%3};"
        : "+f"(c[0]), "+f"(c[1]), "+f"(c[2]), "+f"(c[3])
        : "r"(a[0]), "r"(a[1]), "r"(a[2]), "r"(a[3]), "r"(b0), "r"(b1));
}
__device__ __forceinline__ float fex2(float x) {
    float r;
    asm("ex2.approx.f32 %0, %1;" : "=f"(r) : "f"(x));
    return r;
}
__device__ __forceinline__ void bsplit(float v, __nv_bfloat16& h, __nv_bfloat16& l) {
    h = __float2bfloat16(v);
    l = __float2bfloat16(v - __bfloat162float(h));
}
__device__ __forceinline__ uint32_t bpack(__nv_bfloat16 a, __nv_bfloat16 b) {
    return (uint32_t)__bfloat16_as_ushort(a) |
           ((uint32_t)__bfloat16_as_ushort(b) << 16);
}
__device__ __forceinline__ uint32_t cvt2bf(float h, float l) {
    uint32_t r;
    asm("cvt.rn.bf16x2.f32 %0, %1, %2;" : "=r"(r) : "f"(h), "f"(l));
    return r;
}
__device__ __forceinline__ void cpa16(uint32_t s, const void* g) {
    asm volatile("cp.async.cg.shared.global [%0], [%1], 16;" :: "r"(s), "l"(g));
}
#define CP_COMMIT() asm volatile("cp.async.commit_group;" ::: "memory")
#define CP_WAIT1()  asm volatile("cp.async.wait_group 1;" ::: "memory")

// ===========================================================================
// Scratch (device globals — allocation-free)
// ===========================================================================
__device__ __nv_bfloat16 g_xh[MTOT * DMODEL], g_xl[MTOT * DMODEL];
__device__ __nv_bfloat16 g_wth[4 * DMODEL * DMODEL], g_wtl[4 * DMODEL * DMODEL];
__device__ __nv_bfloat16 g_qkvh[3 * MTOT * DMODEL], g_qkvl[3 * MTOT * DMODEL];
__device__ __nv_bfloat16 g_ah[MTOT * DMODEL], g_al[MTOT * DMODEL];
__device__ float g_bqkv[3 * DMODEL];

// ===========================================================================
// fp32 -> bf16 hi/lo split kernels
// ===========================================================================
__global__ void split_kernel(const float* __restrict__ x,
                             __nv_bfloat16* __restrict__ h,
                             __nv_bfloat16* __restrict__ l, int n) {
    for (int i = blockIdx.x * blockDim.x + threadIdx.x; i < n;
         i += gridDim.x * blockDim.x) {
        __nv_bfloat16 a, b;
        bsplit(x[i], a, b);
        h[i] = a; l[i] = b;
    }
}

__global__ void wsplit4_kernel(const float* __restrict__ W0,
                               const float* __restrict__ W1,
                               const float* __restrict__ W2,
                               const float* __restrict__ W3,
                               __nv_bfloat16* __restrict__ th,
                               __nv_bfloat16* __restrict__ tl) {
    __shared__ float t[32][33];
    const int z = blockIdx.z;
    const float* W = (z == 0) ? W0 : (z == 1) ? W1 : (z == 2) ? W2 : W3;
    __nv_bfloat16* thd = th + (size_t)z * DMODEL * DMODEL;
    __nv_bfloat16* tld = tl + (size_t)z * DMODEL * DMODEL;
    int bx = blockIdx.x * 32, by = blockIdx.y * 32;
    int tx = threadIdx.x, ty = threadIdx.y;
    #pragma unroll
    for (int i = 0; i < 4; i++)
        t[ty + i * 8][tx] = W[(size_t)(by + ty + i * 8) * DMODEL + bx + tx];
    __syncthreads();
    #pragma unroll
    for (int i = 0; i < 4; i++) {
        float v = t[tx][ty + i * 8];
        __nv_bfloat16 h, l;
        bsplit(v, h, l);
        size_t idx = (size_t)(bx + ty + i * 8) * DMODEL + by + tx;
        thd[idx] = h; tld[idx] = l;
    }
}

__global__ void biascat_kernel(const float* __restrict__ a,
                               const float* __restrict__ b,
                               const float* __restrict__ c,
                               float* __restrict__ dst) {
    int i = threadIdx.x;
    dst[i] = a[i];
    dst[DMODEL + i] = b[i];
    dst[2 * DMODEL + i] = c[i];
}

// ===========================================================================
// GEMM v3: cp.async double-buffered, ldmatrix-x4 B operand.
// C[8192, Ncols] = A[8192,512] @ Bt + bias, tile 128(M) x 64(N), 256 thr.
// mode 3: fused QKV epilogue dispatch (cols 0-511 -> Q row-major * QSCALE,
//         512-1023 -> K row-major, 1024-1535 -> V transposed).
// mode 2: fp32 row-major out (O projection).
// ===========================================================================
#define PR_AH 0
#define PR_AL 18432
#define PR_BH 36864
#define PR_BL 46080
#define PR_STG 55296
#define PR_SMEM (2 * PR_STG)   // 110592

__global__ __launch_bounds__(256) void gemm_mma3_kernel(
    const __nv_bfloat16* __restrict__ Ah, const __nv_bfloat16* __restrict__ Al,
    const __nv_bfloat16* __restrict__ Bh, const __nv_bfloat16* __restrict__ Bl,
    const float* __restrict__ bias, int mode,
    __nv_bfloat16* __restrict__ Oh, __nv_bfloat16* __restrict__ Ol,
    float* __restrict__ Of)
{
    extern __shared__ __align__(16) char sm[];
    const uint32_t sb = smem_u32(sm);
    const int tid = threadIdx.x;
    const int lane = tid & 31, wid = tid >> 5;
    const int wm = (wid & 3) * 32, wn = (wid >> 2) * 32;
    const int col0 = blockIdx.x * 64;
    const int row0 = blockIdx.y * 128;
    const int l16 = lane & 15;

    auto load_chunk = [&](int chunk, uint32_t st) {
        const int kc0 = chunk * 64;
        #pragma unroll
        for (int i = 0; i < 4; i++) {
            int u = tid + i * 256;
            int row = u >> 3, c8 = u & 7;
            uint32_t so = (uint32_t)(row * 72 + c8 * 8) * 2;
            size_t g = (size_t)(row0 + row) * DMODEL + kc0 + c8 * 8;
            cpa16(st + PR_AH + so, Ah + g);
            cpa16(st + PR_AL + so, Al + g);
        }
        #pragma unroll
        for (int i = 0; i < 2; i++) {
            int u = tid + i * 256;
            int row = u >> 3, c8 = u & 7;
            uint32_t so = (uint32_t)(row * 72 + c8 * 8) * 2;
            size_t g = (size_t)(col0 + row) * DMODEL + kc0 + c8 * 8;
            cpa16(st + PR_BH + so, Bh + g);
            cpa16(st + PR_BL + so, Bl + g);
        }
    };

    load_chunk(0, sb);          CP_COMMIT();
    load_chunk(1, sb + PR_STG); CP_COMMIT();

    float acc[2][4][4] = {};

    for (int chunk = 0; chunk < 8; chunk++) {
        CP_WAIT1();
        __syncthreads();
        const uint32_t st = sb + (uint32_t)(chunk & 1) * PR_STG;

        #pragma unroll
        for (int ks = 0; ks < 4; ks++) {
            const int kk = ks * 16;
            uint32_t ah[2][4], al2[2][4];
            #pragma unroll
            for (int mt = 0; mt < 2; mt++) {
                uint32_t ad = (uint32_t)((wm + mt * 16 + l16) * 72 + kk + ((lane >> 4) << 3)) * 2;
                ldmx4(ah[mt],  st + PR_AH + ad);
                ldmx4(al2[mt], st + PR_AL + ad);
            }
            #pragma unroll
            for (int np = 0; np < 2; np++) {
                uint32_t bh4[4], bl4[4];
                uint32_t bd = (uint32_t)((wn + np * 16 + (lane & 7) + ((lane >> 4) << 3)) * 72
                                         + kk + (((lane >> 3) & 1) << 3)) * 2;
                ldmx4(bh4, st + PR_BH + bd);
                ldmx4(bl4, st + PR_BL + bd);
                #pragma unroll
                for (int mt = 0; mt < 2; mt++) {
                    mma2(acc[mt][2 * np],     ah[mt],  bh4[0], bh4[1]);
                    mma2(acc[mt][2 * np],     ah[mt],  bl4[0], bl4[1]);
                    mma2(acc[mt][2 * np],     al2[mt], bh4[0], bh4[1]);
                    mma2(acc[mt][2 * np + 1], ah[mt],  bh4[2], bh4[3]);
                    mma2(acc[mt][2 * np + 1], ah[mt],  bl4[2], bl4[3]);
                    mma2(acc[mt][2 * np + 1], al2[mt], bh4[2], bh4[3]);
                }
            }
        }
        __syncthreads();
        if (chunk + 2 < 8) load_chunk(chunk + 2, st);
        CP_COMMIT();
    }

    // Epilogue
    #pragma unroll
    for (int mt = 0; mt < 2; mt++)
        #pragma unroll
        for (int nt = 0; nt < 4; nt++) {
            int cg = col0 + wn + nt * 8 + (lane & 3) * 2;
            float b0 = bias[cg], b1 = bias[cg + 1];
            #pragma unroll
            for (int half = 0; half < 2; half++) {
                int r = row0 + wm + mt * 16 + half * 8 + (lane >> 2);
                float v0 = acc[mt][nt][half * 2]     + b0;
                float v1 = acc[mt][nt][half * 2 + 1] + b1;
                if (mode == 2) {
                    Of[(size_t)r * DMODEL + cg]     = v0;
                    Of[(size_t)r * DMODEL + cg + 1] = v1;
                } else {
                    int seg = cg >> 9, cl = cg & 511;
                    if (seg == 0) { v0 *= QSCALE; v1 *= QSCALE; }
                    __nv_bfloat16 h0, l0, h1, l1;
                    bsplit(v0, h0, l0); bsplit(v1, h1, l1);
                    if (seg < 2) {
                        size_t idx = (size_t)seg * (MTOT * DMODEL) + (size_t)r * DMODEL + cl;
                        *(uint32_t*)(Oh + idx) = bpack(h0, h1);
                        *(uint32_t*)(Ol + idx) = bpack(l0, l1);
                    } else {
                        int s = r & (SEQ - 1), bb = r >> 12;
                        int head = cl >> 6, d = cl & 63;
                        size_t i0 = (size_t)2 * MTOT * DMODEL +
                                    ((size_t)(bb * NHEAD + head) * HEADD + d) * SEQ + s;
                        Oh[i0] = h0;      Ol[i0] = l0;
                        Oh[i0 + SEQ] = h1; Ol[i0 + SEQ] = l1;
                    }
                }
            }
        }
}

// ===========================================================================
// Attention: register-resident P, cp.async double-buffered K/V, exp2 softmax
// (Q pre-scaled by 0.125*log2e). 8 warps x 16 q-rows, 128-key tiles.
// ===========================================================================
#define AB_KH 0
#define AB_KL 18432
#define AB_VH 36864
#define AB_VL 54272
#define AB_SZ 71680
#define AT2_SMEM (2 * AB_SZ)   // 143360

__global__ __launch_bounds__(256) void attn_mma2_kernel(
    const __nv_bfloat16* __restrict__ Qh, const __nv_bfloat16* __restrict__ Ql,
    const __nv_bfloat16* __restrict__ Kh, const __nv_bfloat16* __restrict__ Kl,
    const __nv_bfloat16* __restrict__ Vth, const __nv_bfloat16* __restrict__ Vtl,
    __nv_bfloat16* __restrict__ Ah, __nv_bfloat16* __restrict__ Al)
{
    extern __shared__ __align__(16) char sm[];
    const uint32_t sb = smem_u32(sm);

    const int qt = (SEQ / 128 - 1) - blockIdx.x;   // long blocks first
    const int h = blockIdx.y, b = blockIdx.z;
    const int q0 = qt * 128;
    const int tid = threadIdx.x;
    const int lane = tid & 31, wid = tid >> 5;
    const int r0 = wid * 16;
    const int l16 = lane & 15;

    const size_t kbase = (size_t)(b * SEQ) * DMODEL + h * HEADD;
    const size_t vbase = ((size_t)((b * NHEAD + h) * HEADD)) * SEQ;

    // ---- Prologue: Q tile -> smem (aliases buf0), extract fragments ----
    #pragma unroll
    for (int i = 0; i < 4; i++) {
        int u = tid + i * 256;
        int row = u >> 3, c8 = u & 7;
        uint32_t so = (uint32_t)(row * 144 + c8 * 16);
        size_t g = kbase + (size_t)(q0 + row) * DMODEL + c8 * 8;
        *(uint4*)(sm + so)         = *(const uint4*)(Qh + g);
        *(uint4*)(sm + 18432 + so) = *(const uint4*)(Ql + g);
    }
    __syncthreads();

    uint32_t qfh[4][4], qfl[4][4];
    #pragma unroll
    for (int ks = 0; ks < 4; ks++) {
        uint32_t ad = (uint32_t)((r0 + l16) * 72 + ks * 16 + ((lane >> 4) << 3)) * 2;
        ldmx4(qfh[ks], sb + ad);
        ldmx4(qfl[ks], sb + 18432 + ad);
    }
    __syncthreads();

    // ---- Prefetch tiles 0 and 1 ----
    {
        #pragma unroll
        for (int i = 0; i < 4; i++) {
            int u = tid + i * 256;
            int row = u >> 3, c8 = u & 7;
            uint32_t so = (uint32_t)(row * 144 + c8 * 16);
            cpa16(sb + AB_KH + so, Kh + kbase + (size_t)row * DMODEL + c8 * 8);
            cpa16(sb + AB_KL + so, Kl + kbase + (size_t)row * DMODEL + c8 * 8);
        }
        #pragma unroll
        for (int i = 0; i < 4; i++) {
            int u = tid + i * 256;
            int d = u >> 4, c16 = u & 15;
            uint32_t so = (uint32_t)(d * 272 + c16 * 16);
            cpa16(sb + AB_VH + so, Vth + vbase + (size_t)d * SEQ + c16 * 8);
            cpa16(sb + AB_VL + so, Vtl + vbase + (size_t)d * SEQ + c16 * 8);
        }
        CP_COMMIT();
        if (qt >= 1) {
            const int k0 = 128;
            #pragma unroll
            for (int i = 0; i < 4; i++) {
                int u = tid + i * 256;
                int row = u >> 3, c8 = u & 7;
                uint32_t so = (uint32_t)(row * 144 + c8 * 16);
                cpa16(sb + AB_SZ + AB_KH + so, Kh + kbase + (size_t)(k0 + row) * DMODEL + c8 * 8);
                cpa16(sb + AB_SZ + AB_KL + so, Kl + kbase + (size_t)(k0 + row) * DMODEL + c8 * 8);
            }
            #pragma unroll
            for (int i = 0; i < 4; i++) {
                int u = tid + i * 256;
                int d = u >> 4, c16 = u & 15;
                uint32_t so = (uint32_t)(d * 272 + c16 * 16);
                cpa16(sb + AB_SZ + AB_VH + so, Vth + vbase + (size_t)d * SEQ + k0 + c16 * 8);
                cpa16(sb + AB_SZ + AB_VL + so, Vtl + vbase + (size_t)d * SEQ + k0 + c16 * 8);
            }
        }
        CP_COMMIT();
    }

    float o[8][4] = {};
    float lsA = 0.0f, lsB = 0.0f;
    const int rA = r0 + (lane >> 2);
    const int rB = rA + 8;

    for (int kt = 0; kt <= qt; kt++) {
        const uint32_t buf = sb + (uint32_t)(kt & 1) * AB_SZ;
        CP_WAIT1();
        __syncthreads();

        // --- GEMM1: S[16 x 128] = Q Kt ---
        float s[16][4];
        #pragma unroll
        for (int nt = 0; nt < 16; nt++)
            #pragma unroll
            for (int j = 0; j < 4; j++) s[nt][j] = 0.0f;

        #pragma unroll
        for (int ks = 0; ks < 4; ks++) {
            const int kk = ks * 16;
            #pragma unroll
            for (int np = 0; np < 8; np++) {
                uint32_t bh[4], bl[4];
                uint32_t ad = (uint32_t)((np * 16 + (lane & 7) + ((lane >> 4) << 3)) * 72
                                         + kk + (((lane >> 3) & 1) << 3)) * 2;
                ldmx4(bh, buf + AB_KH + ad);
                ldmx4(bl, buf + AB_KL + ad);
                mma2(s[2 * np],     qfh[ks], bh[0], bh[1]);
                mma2(s[2 * np],     qfh[ks], bl[0], bl[1]);
                mma2(s[2 * np],     qfl[ks], bh[0], bh[1]);
                mma2(s[2 * np + 1], qfh[ks], bh[2], bh[3]);
                mma2(s[2 * np + 1], qfh[ks], bl[2], bl[3]);
                mma2(s[2 * np + 1], qfl[ks], bh[2], bh[3]);
            }
        }

        // --- Softmax numerator (exp2, no max) + causal mask + P frags ---
        const bool diag = (kt == qt);
        uint32_t ph[16][2], pl[16][2];
        #pragma unroll
        for (int nt = 0; nt < 16; nt++) {
            const int cg = nt * 8 + (lane & 3) * 2;
            float p0 = fex2(s[nt][0]);
            float p1 = fex2(s[nt][1]);
            float p2 = fex2(s[nt][2]);
            float p3 = fex2(s[nt][3]);
            if (diag) {
                if (cg > rA)     p0 = 0.0f;
                if (cg + 1 > rA) p1 = 0.0f;
                if (cg > rB)     p2 = 0.0f;
                if (cg + 1 > rB) p3 = 0.0f;
            }
            lsA += p0 + p1;
            lsB += p2 + p3;
            uint32_t h01 = cvt2bf(p1, p0);
            uint32_t h23 = cvt2bf(p3, p2);
            ph[nt][0] = h01; ph[nt][1] = h23;
            float f0 = __uint_as_float(h01 << 16);
            float f1 = __uint_as_float(h01 & 0xFFFF0000u);
            float f2 = __uint_as_float(h23 << 16);
            float f3 = __uint_as_float(h23 & 0xFFFF0000u);
            pl[nt][0] = cvt2bf(p1 - f1, p0 - f0);
            pl[nt][1] = cvt2bf(p3 - f3, p2 - f2);
        }

        // --- GEMM2: O[16 x 64] += P V ---
        #pragma unroll
        for (int kc = 0; kc < 8; kc++) {
            uint32_t pah[4] = {ph[2 * kc][0], ph[2 * kc][1],
                               ph[2 * kc + 1][0], ph[2 * kc + 1][1]};
            uint32_t pal[4] = {pl[2 * kc][0], pl[2 * kc][1],
                               pl[2 * kc + 1][0], pl[2 * kc + 1][1]};
            #pragma unroll
            for (int np = 0; np < 4; np++) {
                uint32_t vh[4], vl[4];
                uint32_t ad = (uint32_t)((np * 16 + (lane & 7) + ((lane >> 4) << 3)) * 136
                                         + kc * 16 + (((lane >> 3) & 1) << 3)) * 2;
                ldmx4(vh, buf + AB_VH + ad);
                ldmx4(vl, buf + AB_VL + ad);
                mma2(o[2 * np],     pah, vh[0], vh[1]);
                mma2(o[2 * np],     pah, vl[0], vl[1]);
                mma2(o[2 * np],     pal, vh[0], vh[1]);
                mma2(o[2 * np + 1], pah, vh[2], vh[3]);
                mma2(o[2 * np + 1], pah, vl[2], vl[3]);
                mma2(o[2 * np + 1], pal, vh[2], vh[3]);
            }
        }

        __syncthreads();

        // --- Prefetch tile kt+2 ---
        if (kt + 2 <= qt) {
            const int k0 = (kt + 2) * 128;
            #pragma unroll
            for (int i = 0; i < 4; i++) {
                int u = tid + i * 256;
                int row = u >> 3, c8 = u & 7;
                uint32_t so = (uint32_t)(row * 144 + c8 * 16);
                cpa16(buf + AB_KH + so, Kh + kbase + (size_t)(k0 + row) * DMODEL + c8 * 8);
                cpa16(buf + AB_KL + so, Kl + kbase + (size_t)(k0 + row) * DMODEL + c8 * 8);
            }
            #pragma unroll
            for (int i = 0; i < 4; i++) {
                int u = tid + i * 256;
                int d = u >> 4, c16 = u & 15;
                uint32_t so = (uint32_t)(d * 272 + c16 * 16);
                cpa16(buf + AB_VH + so, Vth + vbase + (size_t)d * SEQ + k0 + c16 * 8);
                cpa16(buf + AB_VL + so, Vtl + vbase + (size_t)d * SEQ + k0 + c16 * 8);
            }
        }
        CP_COMMIT();
    }

    // --- Row sums: reduce across the 4 column-owner lanes ---
    lsA += __shfl_xor_sync(0xFFFFFFFFu, lsA, 1);
    lsA += __shfl_xor_sync(0xFFFFFFFFu, lsA, 2);
    lsB += __shfl_xor_sync(0xFFFFFFFFu, lsB, 1);
    lsB += __shfl_xor_sync(0xFFFFFFFFu, lsB, 2);
    const float liA = 1.0f / lsA;
    const float liB = 1.0f / lsB;

    // --- Epilogue ---
    #pragma unroll
    for (int nt = 0; nt < 8; nt++) {
        const int dd = nt * 8 + (lane & 3) * 2;
        float v0 = o[nt][0] * liA, v1 = o[nt][1] * liA;
        float v2 = o[nt][2] * liB, v3 = o[nt][3] * liB;
        __nv_bfloat16 h0, l0, h1, l1;
        bsplit(v0, h0, l0); bsplit(v1, h1, l1);
        size_t iA = (size_t)(b * SEQ + q0 + rA) * DMODEL + h * HEADD + dd;
        *(uint32_t*)(Ah + iA) = bpack(h0, h1);
        *(uint32_t*)(Al + iA) = bpack(l0, l1);
        bsplit(v2, h0, l0); bsplit(v3, h1, l1);
        size_t iB = (size_t)(b * SEQ + q0 + rB) * DMODEL + h * HEADD + dd;
        *(uint32_t*)(Ah + iB) = bpack(h0, h1);
        *(uint32_t*)(Al + iB) = bpack(l0, l1);
    }
}

// ===========================================================================
// Launch
// ===========================================================================
extern "C" void kernel_launch(void* const* d_in, const int* in_sizes, int n_in,
                              void* d_out, int out_size)
{
    const float* x  = (const float*)d_in[0];
    const float* Wq = (const float*)d_in[1];
    const float* bq = (const float*)d_in[2];
    const float* Wk = (const float*)d_in[3];
    const float* bk = (const float*)d_in[4];
    const float* Wv = (const float*)d_in[5];
    const float* bv = (const float*)d_in[6];
    const float* Wo = (const float*)d_in[7];
    const float* bo = (const float*)d_in[8];
    float* out = (float*)d_out;

    __nv_bfloat16 *xh, *xl, *wth, *wtl, *qkvh, *qkvl, *ah, *al;
    float* bqkv;
    cudaGetSymbolAddress((void**)&xh,   g_xh);
    cudaGetSymbolAddress((void**)&xl,   g_xl);
    cudaGetSymbolAddress((void**)&wth,  g_wth);
    cudaGetSymbolAddress((void**)&wtl,  g_wtl);
    cudaGetSymbolAddress((void**)&qkvh, g_qkvh);
    cudaGetSymbolAddress((void**)&qkvl, g_qkvl);
    cudaGetSymbolAddress((void**)&ah,   g_ah);
    cudaGetSymbolAddress((void**)&al,   g_al);
    cudaGetSymbolAddress((void**)&bqkv, g_bqkv);

    cudaFuncSetAttribute(gemm_mma3_kernel,
                         cudaFuncAttributeMaxDynamicSharedMemorySize, PR_SMEM);
    cudaFuncSetAttribute(attn_mma2_kernel,
                         cudaFuncAttributeMaxDynamicSharedMemorySize, AT2_SMEM);

    const int WSZ = DMODEL * DMODEL;

    split_kernel<<<2048, 256>>>(x, xh, xl, MTOT * DMODEL);
    dim3 wb(32, 8), wg(16, 16, 4);
    wsplit4_kernel<<<wg, wb>>>(Wq, Wk, Wv, Wo, wth, wtl);
    biascat_kernel<<<1, DMODEL>>>(bq, bk, bv, bqkv);

    // Fused QKV projection: 8192 x 1536
    dim3 gq(3 * DMODEL / 64, MTOT / 128);   // (24, 64)
    gemm_mma3_kernel<<<gq, 256, PR_SMEM>>>(xh, xl, wth, wtl, bqkv, 3,
                                           qkvh, qkvl, nullptr);

    const __nv_bfloat16* qh  = qkvh;
    const __nv_bfloat16* ql  = qkvl;
    const __nv_bfloat16* kh  = qkvh + (size_t)MTOT * DMODEL;
    const __nv_bfloat16* kl  = qkvl + (size_t)MTOT * DMODEL;
    const __nv_bfloat16* vth = qkvh + (size_t)2 * MTOT * DMODEL;
    const __nv_bfloat16* vtl = qkvl + (size_t)2 * MTOT * DMODEL;

    dim3 ag(SEQ / 128, NHEAD, BATCH);   // (32, 8, 2)
    attn_mma2_kernel<<<ag, 256, AT2_SMEM>>>(qh, ql, kh, kl, vth, vtl, ah, al);

    // Output projection: 8192 x 512, fp32 out
    dim3 go(DMODEL / 64, MTOT / 128);   // (8, 64)
    gemm_mma3_kernel<<<go, 256, PR_SMEM>>>(ah, al, wth + 3 * WSZ, wtl + 3 * WSZ,
                                           bo, 2, nullptr, nullptr, out);
}